// round 7
// baseline (speedup 1.0000x reference)
#include <cuda_runtime.h>
#include <cuda_bf16.h>

#define NTOK 16384
#define INF  512
#define HID  256
#define OUTF 16
#define NSTEPS 16
#define SIGMA2F 0.1f
#define KT_TOTAL (NTOK / 16)           // 1024 k-tiles
#define RT_TOTAL (NTOK / 16)           // 1024 row-tiles
#define UNITS 2048                     // 128 rt-groups x 16 k-groups
#define KT_PER_UNIT 64                 // k-tiles per unit (1024 k)

// Scratch (device globals: sanctioned, no allocation)
// g_Lbf: L fragment-major: tile (rt,kt) -> 512B at ((rt*1024+kt)*512), lane l -> uint4
__device__ __align__(16) __nv_bfloat16 g_Lbf[(size_t)NTOK * NTOK];       // 512 MB
__device__ __align__(16) float          g_U[2][NTOK * OUTF];             // u fp32, row-major
__device__ __align__(16) __nv_bfloat16  g_Bfrag[2][OUTF * NTOK];         // u bf16 B-fragment-major
__device__ __align__(16) float          g_P[NTOK * OUTF];                // partials (zero at steady state)
__device__ unsigned                     g_ticket[NSTEPS];                // zero at steady state

// ---------------------------------------------------------------------------
// Helper: write one fp32 value (row r, col c) into B-fragment layout as bf16
// ---------------------------------------------------------------------------
__device__ __forceinline__ void write_bfrag(__nv_bfloat16* Bf, int r, int c, float v) {
    const int s = r >> 4, p = r & 15;
    const int g = c & 7;
    const int tt = (p & 7) >> 1;
    const int word = (p >> 3) + 2 * (c >> 3);
    const int lane = g * 4 + tt;
    Bf[s * 256 + lane * 8 + word * 2 + (p & 1)] = __float2bfloat16(v);
}

// ---------------------------------------------------------------------------
// Kernel 1: convert L fp32 -> bf16 fragment-major, via coalesced smem staging.
// CTA = 16 rows x 256 cols block. Load coalesced float4; warps emit 2 tiles each.
// ---------------------------------------------------------------------------
#define CV_PAD 264   // floats per smem row (256 + 8 pad)
__global__ void __launch_bounds__(256) convert_L(const float* __restrict__ L) {
    __shared__ float s[16][CV_PAD];   // ~16.9 KB
    const int blk = blockIdx.x;       // 0..65535
    const int rt = blk >> 6;          // row-tile
    const int kg = blk & 63;          // 256-col group
    const int tid = threadIdx.x;

    // coalesced load: 16 rows x 64 float4
    const float* __restrict__ src = L + (size_t)rt * 16 * NTOK + kg * 256;
    #pragma unroll 4
    for (int j = tid; j < 16 * 64; j += 256) {
        const int row = j >> 6, c4 = j & 63;
        const float4 v = __ldcs((const float4*)(src + (size_t)row * NTOK + c4 * 4));
        *(float4*)&s[row][c4 * 4] = v;
    }
    __syncthreads();

    const int warp = tid >> 5, lane = tid & 31;
    const int g = lane >> 2, t = lane & 3;
    #pragma unroll
    for (int i = 0; i < 2; i++) {
        const int ktl = warp * 2 + i;          // local k-tile 0..15
        const int kt = kg * 16 + ktl;          // global k-tile
        const int c = ktl * 16 + 2 * t;
        const float2 w0 = *(const float2*)&s[g][c];
        const float2 w1 = *(const float2*)&s[g + 8][c];
        const float2 w2 = *(const float2*)&s[g][c + 8];
        const float2 w3 = *(const float2*)&s[g + 8][c + 8];
        __nv_bfloat162 b0 = __floats2bfloat162_rn(w0.x, w0.y);
        __nv_bfloat162 b1 = __floats2bfloat162_rn(w1.x, w1.y);
        __nv_bfloat162 b2 = __floats2bfloat162_rn(w2.x, w2.y);
        __nv_bfloat162 b3 = __floats2bfloat162_rn(w3.x, w3.y);
        uint4 o;
        o.x = *reinterpret_cast<unsigned*>(&b0);
        o.y = *reinterpret_cast<unsigned*>(&b1);
        o.z = *reinterpret_cast<unsigned*>(&b2);
        o.w = *reinterpret_cast<unsigned*>(&b3);
        reinterpret_cast<uint4*>(g_Lbf)[((size_t)rt * KT_TOTAL + kt) * 32 + lane] = o;
    }
}

// ---------------------------------------------------------------------------
// Kernel 2: u0 = (f @ Ws + bs) + (elu(f @ W1 + b1) @ W2 + b2)
// ---------------------------------------------------------------------------
__global__ void __launch_bounds__(256) init_u0(
    const float* __restrict__ F,  const float* __restrict__ W1, const float* __restrict__ b1,
    const float* __restrict__ W2, const float* __restrict__ b2,
    const float* __restrict__ Ws, const float* __restrict__ bs)
{
    __shared__ float fs[8][INF];   // 16 KB
    __shared__ float hs[8][HID];   // 8 KB
    const int tid = threadIdx.x;
    const int rbase = blockIdx.x * 8;

    {
        const float4* Fv = (const float4*)(F + (size_t)rbase * INF);
        float4* fsv = (float4*)&fs[0][0];
        #pragma unroll 4
        for (int i = tid; i < 8 * INF / 4; i += 256) fsv[i] = Fv[i];
    }
    __syncthreads();

    {
        const int j = tid;  // 0..255
        float acc[8];
        const float bb = b1[j];
        #pragma unroll
        for (int rr = 0; rr < 8; rr++) acc[rr] = bb;
        #pragma unroll 4
        for (int k = 0; k < INF; k++) {
            const float w = W1[k * HID + j];
            #pragma unroll
            for (int rr = 0; rr < 8; rr++) acc[rr] = fmaf(fs[rr][k], w, acc[rr]);
        }
        #pragma unroll
        for (int rr = 0; rr < 8; rr++) {
            const float x = acc[rr];
            hs[rr][j] = x > 0.0f ? x : expm1f(x);
        }
    }
    __syncthreads();

    if (tid < 8 * OUTF) {
        const int rr = tid >> 4, c = tid & 15;
        float s0 = bs[c] + b2[c], s1 = 0.f, s2 = 0.f, s3 = 0.f;
        #pragma unroll 4
        for (int k = 0; k < INF; k += 4) {
            s0 = fmaf(fs[rr][k + 0], Ws[(k + 0) * OUTF + c], s0);
            s1 = fmaf(fs[rr][k + 1], Ws[(k + 1) * OUTF + c], s1);
            s2 = fmaf(fs[rr][k + 2], Ws[(k + 2) * OUTF + c], s2);
            s3 = fmaf(fs[rr][k + 3], Ws[(k + 3) * OUTF + c], s3);
        }
        #pragma unroll 4
        for (int j = 0; j < HID; j += 4) {
            s0 = fmaf(hs[rr][j + 0], W2[(j + 0) * OUTF + c], s0);
            s1 = fmaf(hs[rr][j + 1], W2[(j + 1) * OUTF + c], s1);
            s2 = fmaf(hs[rr][j + 2], W2[(j + 2) * OUTF + c], s2);
            s3 = fmaf(hs[rr][j + 3], W2[(j + 3) * OUTF + c], s3);
        }
        const float s = (s0 + s1) + (s2 + s3);
        const int r = rbase + rr;
        g_U[0][r * OUTF + c] = s;
        write_bfrag(g_Bfrag[0], r, c, s);
    }
}

// ---------------------------------------------------------------------------
// Kernel 3: partial GEMM, persistent CTAs + dynamic ticket over 2048 units.
// Unit = 8 row-tiles (1 per warp) x 64 k-tiles. B frags staged in smem per unit.
// ---------------------------------------------------------------------------
__device__ __forceinline__ void mma16816(float d[4], const uint4 a, const unsigned b0, const unsigned b1) {
    asm volatile(
        "mma.sync.aligned.m16n8k16.row.col.f32.bf16.bf16.f32 "
        "{%0,%1,%2,%3}, {%4,%5,%6,%7}, {%8,%9}, {%0,%1,%2,%3};\n"
        : "+f"(d[0]), "+f"(d[1]), "+f"(d[2]), "+f"(d[3])
        : "r"(a.x), "r"(a.y), "r"(a.z), "r"(a.w), "r"(b0), "r"(b1));
}

__global__ void __launch_bounds__(256, 6) step_partial(int inb, int step) {
    __shared__ uint4 sB[KT_PER_UNIT * 32];   // 32 KB
    __shared__ unsigned s_t;

    const int tid  = threadIdx.x;
    const int warp = tid >> 5;
    const int lane = tid & 31;
    const int g = lane >> 2, t2 = 2 * (lane & 3);

    for (;;) {
        if (tid == 0) s_t = atomicAdd(&g_ticket[step], 1u);
        __syncthreads();
        const unsigned u = s_t;
        if (u >= UNITS) return;

        const int kg  = u >> 7;          // 0..15  (consecutive tickets share kg -> B hot in L2)
        const int rtg = u & 127;         // 0..127
        const int kt0 = kg * KT_PER_UNIT;
        const int rt  = rtg * 8 + warp;

        // stage B fragments for this k-range
        {
            const uint4* __restrict__ Bg = reinterpret_cast<const uint4*>(g_Bfrag[inb]) + kt0 * 32;
            #pragma unroll 2
            for (int i = tid; i < KT_PER_UNIT * 32; i += 256) sB[i] = Bg[i];
        }
        __syncthreads();

        const uint4* __restrict__ Af =
            reinterpret_cast<const uint4*>(g_Lbf) + ((size_t)rt * KT_TOTAL + kt0) * 32 + lane;

        float d0[4] = {0.f, 0.f, 0.f, 0.f};
        float d1[4] = {0.f, 0.f, 0.f, 0.f};

        for (int c = 0; c < KT_PER_UNIT; c += 4) {
            uint4 a0 = __ldcs(Af + (c + 0) * 32);
            uint4 a1 = __ldcs(Af + (c + 1) * 32);
            uint4 a2 = __ldcs(Af + (c + 2) * 32);
            uint4 a3 = __ldcs(Af + (c + 3) * 32);

            uint4 b;
            b = sB[(c + 0) * 32 + lane]; mma16816(d0, a0, b.x, b.y); mma16816(d1, a0, b.z, b.w);
            b = sB[(c + 1) * 32 + lane]; mma16816(d0, a1, b.x, b.y); mma16816(d1, a1, b.z, b.w);
            b = sB[(c + 2) * 32 + lane]; mma16816(d0, a2, b.x, b.y); mma16816(d1, a2, b.z, b.w);
            b = sB[(c + 3) * 32 + lane]; mma16816(d0, a3, b.x, b.y); mma16816(d1, a3, b.z, b.w);
        }

        const int r0 = rt * 16 + g, r1 = r0 + 8;
        #pragma unroll
        for (int h = 0; h < 2; h++) {
            const float* dd = h ? d1 : d0;
            const int cc = t2 + 8 * h;
            atomicAdd(&g_P[r0 * OUTF + cc],     dd[0]);
            atomicAdd(&g_P[r0 * OUTF + cc + 1], dd[1]);
            atomicAdd(&g_P[r1 * OUTF + cc],     dd[2]);
            atomicAdd(&g_P[r1 * OUTF + cc + 1], dd[3]);
        }
        __syncthreads();   // protect sB and s_t before next unit
    }
}

// ---------------------------------------------------------------------------
// Kernel 4: finalize. u_out = u_in - sigma2 * P; rezero P; emit B-frags;
// rezero this step's ticket counter. 2 threads per row.
// ---------------------------------------------------------------------------
__global__ void __launch_bounds__(256) step_finalize(int inb, int outb, int step, float* final_dst) {
    const int idx = blockIdx.x * 256 + threadIdx.x;   // 0..32767
    const int r = idx >> 1;
    const int c0 = (idx & 1) * 8;
    if (idx == 0) g_ticket[step] = 0u;

    const float* __restrict__ Ui = g_U[inb] + r * OUTF + c0;
    float* __restrict__ Uo = g_U[outb] + r * OUTF + c0;
    float* __restrict__ P  = g_P + r * OUTF + c0;

    float v[8];
    #pragma unroll
    for (int i = 0; i < 2; i++) {
        float4 u4 = *(const float4*)(Ui + 4 * i);
        float4 p4 = *(const float4*)(P + 4 * i);
        v[4*i+0] = u4.x - SIGMA2F * p4.x;
        v[4*i+1] = u4.y - SIGMA2F * p4.y;
        v[4*i+2] = u4.z - SIGMA2F * p4.z;
        v[4*i+3] = u4.w - SIGMA2F * p4.w;
        *(float4*)(Uo + 4 * i) = make_float4(v[4*i+0], v[4*i+1], v[4*i+2], v[4*i+3]);
        *(float4*)(P + 4 * i) = make_float4(0.f, 0.f, 0.f, 0.f);
        if (final_dst) *(float4*)(final_dst + r * OUTF + c0 + 4 * i)
            = make_float4(v[4*i+0], v[4*i+1], v[4*i+2], v[4*i+3]);
    }
    __nv_bfloat16* __restrict__ Bf = g_Bfrag[outb];
    #pragma unroll
    for (int c = 0; c < 8; c++) write_bfrag(Bf, r, c0 + c, v[c]);
}

// ---------------------------------------------------------------------------
extern "C" void kernel_launch(void* const* d_in, const int* in_sizes, int n_in,
                              void* d_out, int out_size) {
    const float* F  = (const float*)d_in[0];
    const float* L  = (const float*)d_in[1];
    const float* W1 = (const float*)d_in[2];
    const float* b1 = (const float*)d_in[3];
    const float* W2 = (const float*)d_in[4];
    const float* b2 = (const float*)d_in[5];
    const float* Ws = (const float*)d_in[6];
    const float* bs = (const float*)d_in[7];

    convert_L<<<RT_TOTAL * 64, 256>>>(L);   // 65536 CTAs: 16x256 block each
    init_u0<<<NTOK / 8, 256>>>(F, W1, b1, W2, b2, Ws, bs);
    for (int s = 0; s < NSTEPS; s++) {
        step_partial<<<148 * 6, 256>>>(s & 1, s);
        step_finalize<<<NTOK * 2 / 256, 256>>>(s & 1, (s + 1) & 1, s,
                                               s == NSTEPS - 1 ? (float*)d_out : nullptr);
    }
}

// round 8
// speedup vs baseline: 1.5509x; 1.5509x over previous
#include <cuda_runtime.h>
#include <cuda_bf16.h>
#include <cuda_fp16.h>

#define NTOK 16384
#define INF  512
#define HID  256
#define OUTF 16
#define NSTEPS 16
#define SIGMA2F 0.1f
#define LSCALE 16384.0f                 // 2^14: lifts L into e4m3 range
#define FIN_SCALE (SIGMA2F / LSCALE)
#define KSPLITS 16
#define KSEG (NTOK / KSPLITS)          // 1024
#define KT_TOTAL (NTOK / 16)           // 1024 k-tiles
#define RT_TOTAL (NTOK / 16)           // 1024 row-tiles
#define SLICES_PER_CTA (KSEG / 16)     // 64

// Scratch (device globals: sanctioned, no allocation)
// g_L8: L in e4m3 fragment-major: tile (rt,kt) -> 256B block, lane l -> uint2
//   uint2.x = {pairA1(hi16), pairA0(lo16)}, uint2.y = {pairA3, pairA2}
//   pairAi packs (k even -> low byte, k odd -> high byte), matching f16x2 cvt.
__device__ __align__(16) uint2   g_L8[(size_t)RT_TOTAL * KT_TOTAL * 32];  // 256 MB
__device__ __align__(16) float   g_U[2][NTOK * OUTF];                     // u fp32, row-major
__device__ __align__(16) __half  g_Bfrag[2][OUTF * NTOK];                 // u f16 B-fragment-major
__device__ __align__(16) float   g_P[NTOK * OUTF];                        // partials (zero at steady state)

// ---------------------------------------------------------------------------
__device__ __forceinline__ unsigned short e4m3x2_pack(float hi, float lo) {
    unsigned short r;
    asm("cvt.rn.satfinite.e4m3x2.f32 %0, %1, %2;" : "=h"(r) : "f"(hi), "f"(lo));
    return r;
}
__device__ __forceinline__ unsigned f16x2_from_e4m3x2(unsigned short b) {
    unsigned r;
    asm("cvt.rn.f16x2.e4m3x2 %0, %1;" : "=r"(r) : "h"(b));
    return r;
}

// Helper: write one fp32 value (row r, col c) into f16 B-fragment layout
__device__ __forceinline__ void write_bfrag(__half* Bf, int r, int c, float v) {
    const int s = r >> 4, p = r & 15;
    const int g = c & 7;
    const int tt = (p & 7) >> 1;
    const int word = (p >> 3) + 2 * (c >> 3);
    const int lane = g * 4 + tt;
    Bf[s * 256 + lane * 8 + word * 2 + (p & 1)] = __float2half(v);
}

// ---------------------------------------------------------------------------
// Kernel 1: convert L fp32 -> e4m3 fragment-major (x LSCALE), smem staged.
// CTA = 16 rows x 256 cols. Coalesced loads; each warp emits 2 tiles.
// ---------------------------------------------------------------------------
#define CV_PAD 264
__global__ void __launch_bounds__(256) convert_L(const float* __restrict__ L) {
    __shared__ float s[16][CV_PAD];
    const int blk = blockIdx.x;       // 0..65535
    const int rt = blk >> 6;
    const int kg = blk & 63;
    const int tid = threadIdx.x;

    const float* __restrict__ src = L + (size_t)rt * 16 * NTOK + kg * 256;
    #pragma unroll 4
    for (int j = tid; j < 16 * 64; j += 256) {
        const int row = j >> 6, c4 = j & 63;
        const float4 v = __ldcs((const float4*)(src + (size_t)row * NTOK + c4 * 4));
        *(float4*)&s[row][c4 * 4] = v;
    }
    __syncthreads();

    const int warp = tid >> 5, lane = tid & 31;
    const int g = lane >> 2, t = lane & 3;
    #pragma unroll
    for (int i = 0; i < 2; i++) {
        const int ktl = warp * 2 + i;          // local k-tile 0..15
        const int kt = kg * 16 + ktl;
        const int c = ktl * 16 + 2 * t;
        const float2 w0 = *(const float2*)&s[g][c];        // a0 pair (k, k+1)
        const float2 w1 = *(const float2*)&s[g + 8][c];    // a1
        const float2 w2 = *(const float2*)&s[g][c + 8];    // a2
        const float2 w3 = *(const float2*)&s[g + 8][c + 8];// a3
        const unsigned short p0 = e4m3x2_pack(w0.y * LSCALE, w0.x * LSCALE);
        const unsigned short p1 = e4m3x2_pack(w1.y * LSCALE, w1.x * LSCALE);
        const unsigned short p2 = e4m3x2_pack(w2.y * LSCALE, w2.x * LSCALE);
        const unsigned short p3 = e4m3x2_pack(w3.y * LSCALE, w3.x * LSCALE);
        uint2 o;
        o.x = (unsigned)p0 | ((unsigned)p1 << 16);
        o.y = (unsigned)p2 | ((unsigned)p3 << 16);
        g_L8[((size_t)rt * KT_TOTAL + kt) * 32 + lane] = o;
    }
}

// ---------------------------------------------------------------------------
// Kernel 2: u0 = (f @ Ws + bs) + (elu(f @ W1 + b1) @ W2 + b2)
// ---------------------------------------------------------------------------
__global__ void __launch_bounds__(256) init_u0(
    const float* __restrict__ F,  const float* __restrict__ W1, const float* __restrict__ b1,
    const float* __restrict__ W2, const float* __restrict__ b2,
    const float* __restrict__ Ws, const float* __restrict__ bs)
{
    __shared__ float fs[8][INF];   // 16 KB
    __shared__ float hs[8][HID];   // 8 KB
    const int tid = threadIdx.x;
    const int rbase = blockIdx.x * 8;

    {
        const float4* Fv = (const float4*)(F + (size_t)rbase * INF);
        float4* fsv = (float4*)&fs[0][0];
        #pragma unroll 4
        for (int i = tid; i < 8 * INF / 4; i += 256) fsv[i] = Fv[i];
    }
    __syncthreads();

    {
        const int j = tid;  // 0..255
        float acc[8];
        const float bb = b1[j];
        #pragma unroll
        for (int rr = 0; rr < 8; rr++) acc[rr] = bb;
        #pragma unroll 4
        for (int k = 0; k < INF; k++) {
            const float w = W1[k * HID + j];
            #pragma unroll
            for (int rr = 0; rr < 8; rr++) acc[rr] = fmaf(fs[rr][k], w, acc[rr]);
        }
        #pragma unroll
        for (int rr = 0; rr < 8; rr++) {
            const float x = acc[rr];
            hs[rr][j] = x > 0.0f ? x : expm1f(x);
        }
    }
    __syncthreads();

    if (tid < 8 * OUTF) {
        const int rr = tid >> 4, c = tid & 15;
        float s0 = bs[c] + b2[c], s1 = 0.f, s2 = 0.f, s3 = 0.f;
        #pragma unroll 4
        for (int k = 0; k < INF; k += 4) {
            s0 = fmaf(fs[rr][k + 0], Ws[(k + 0) * OUTF + c], s0);
            s1 = fmaf(fs[rr][k + 1], Ws[(k + 1) * OUTF + c], s1);
            s2 = fmaf(fs[rr][k + 2], Ws[(k + 2) * OUTF + c], s2);
            s3 = fmaf(fs[rr][k + 3], Ws[(k + 3) * OUTF + c], s3);
        }
        #pragma unroll 4
        for (int j = 0; j < HID; j += 4) {
            s0 = fmaf(hs[rr][j + 0], W2[(j + 0) * OUTF + c], s0);
            s1 = fmaf(hs[rr][j + 1], W2[(j + 1) * OUTF + c], s1);
            s2 = fmaf(hs[rr][j + 2], W2[(j + 2) * OUTF + c], s2);
            s3 = fmaf(hs[rr][j + 3], W2[(j + 3) * OUTF + c], s3);
        }
        const float s = (s0 + s1) + (s2 + s3);
        const int r = rbase + rr;
        g_U[0][r * OUTF + c] = s;
        write_bfrag(g_Bfrag[0], r, c, s);
    }
}

// ---------------------------------------------------------------------------
// Kernel 3: partial GEMM (K-split), static grid (128, 16), 8 warps/CTA.
// A: fp8 frag (one LDG.64 / 16x16 tile) -> f16 in-register. B: f16 frags in smem.
// ---------------------------------------------------------------------------
__device__ __forceinline__ void mma16816h(float d[4], unsigned a0, unsigned a1,
                                          unsigned a2, unsigned a3,
                                          unsigned b0, unsigned b1) {
    asm volatile(
        "mma.sync.aligned.m16n8k16.row.col.f32.f16.f16.f32 "
        "{%0,%1,%2,%3}, {%4,%5,%6,%7}, {%8,%9}, {%0,%1,%2,%3};\n"
        : "+f"(d[0]), "+f"(d[1]), "+f"(d[2]), "+f"(d[3])
        : "r"(a0), "r"(a1), "r"(a2), "r"(a3), "r"(b0), "r"(b1));
}

__global__ void __launch_bounds__(256, 6) step_partial(int inb) {
    __shared__ uint4 sB[SLICES_PER_CTA * 32];   // 32 KB: f16 B frags for this K-range

    const int tid  = threadIdx.x;
    const int warp = tid >> 5;
    const int lane = tid & 31;

    const int rt  = blockIdx.x * 8 + warp;              // row-tile 0..1023
    const int kt0 = blockIdx.y * SLICES_PER_CTA;        // first k-tile

    {
        const uint4* __restrict__ Bg = reinterpret_cast<const uint4*>(g_Bfrag[inb]) + kt0 * 32;
        #pragma unroll 2
        for (int i = tid; i < SLICES_PER_CTA * 32; i += 256) sB[i] = Bg[i];
    }
    __syncthreads();

    const uint2* __restrict__ Af = g_L8 + ((size_t)rt * KT_TOTAL + kt0) * 32 + lane;

    float d0[4] = {0.f, 0.f, 0.f, 0.f};
    float d1[4] = {0.f, 0.f, 0.f, 0.f};

    for (int c = 0; c < SLICES_PER_CTA; c += 4) {
        uint2 w0 = __ldcs(Af + (c + 0) * 32);
        uint2 w1 = __ldcs(Af + (c + 1) * 32);
        uint2 w2 = __ldcs(Af + (c + 2) * 32);
        uint2 w3 = __ldcs(Af + (c + 3) * 32);

        #pragma unroll
        for (int q = 0; q < 4; q++) {
            const uint2 w = q == 0 ? w0 : q == 1 ? w1 : q == 2 ? w2 : w3;
            const unsigned a0 = f16x2_from_e4m3x2((unsigned short)(w.x));
            const unsigned a1 = f16x2_from_e4m3x2((unsigned short)(w.x >> 16));
            const unsigned a2 = f16x2_from_e4m3x2((unsigned short)(w.y));
            const unsigned a3 = f16x2_from_e4m3x2((unsigned short)(w.y >> 16));
            const uint4 b = sB[(c + q) * 32 + lane];
            mma16816h(d0, a0, a1, a2, a3, b.x, b.y);
            mma16816h(d1, a0, a1, a2, a3, b.z, b.w);
        }
    }

    const int g = lane >> 2, t2 = 2 * (lane & 3);
    const int r0 = rt * 16 + g, r1 = r0 + 8;
    #pragma unroll
    for (int h = 0; h < 2; h++) {
        const float* dd = h ? d1 : d0;
        const int cc = t2 + 8 * h;
        atomicAdd(&g_P[r0 * OUTF + cc],     dd[0]);
        atomicAdd(&g_P[r0 * OUTF + cc + 1], dd[1]);
        atomicAdd(&g_P[r1 * OUTF + cc],     dd[2]);
        atomicAdd(&g_P[r1 * OUTF + cc + 1], dd[3]);
    }
}

// ---------------------------------------------------------------------------
// Kernel 4: finalize. u_out = u_in - (sigma2/LSCALE) * P; rezero P; emit B-frags.
// 2 threads per row.
// ---------------------------------------------------------------------------
__global__ void __launch_bounds__(256) step_finalize(int inb, int outb, float* final_dst) {
    const int idx = blockIdx.x * 256 + threadIdx.x;   // 0..32767
    const int r = idx >> 1;
    const int c0 = (idx & 1) * 8;

    const float* __restrict__ Ui = g_U[inb] + r * OUTF + c0;
    float* __restrict__ Uo = g_U[outb] + r * OUTF + c0;
    float* __restrict__ P  = g_P + r * OUTF + c0;

    float v[8];
    #pragma unroll
    for (int i = 0; i < 2; i++) {
        float4 u4 = *(const float4*)(Ui + 4 * i);
        float4 p4 = *(const float4*)(P + 4 * i);
        v[4*i+0] = u4.x - FIN_SCALE * p4.x;
        v[4*i+1] = u4.y - FIN_SCALE * p4.y;
        v[4*i+2] = u4.z - FIN_SCALE * p4.z;
        v[4*i+3] = u4.w - FIN_SCALE * p4.w;
        *(float4*)(Uo + 4 * i) = make_float4(v[4*i+0], v[4*i+1], v[4*i+2], v[4*i+3]);
        *(float4*)(P + 4 * i) = make_float4(0.f, 0.f, 0.f, 0.f);
        if (final_dst) *(float4*)(final_dst + r * OUTF + c0 + 4 * i)
            = make_float4(v[4*i+0], v[4*i+1], v[4*i+2], v[4*i+3]);
    }
    __half* __restrict__ Bf = g_Bfrag[outb];
    #pragma unroll
    for (int c = 0; c < 8; c++) write_bfrag(Bf, r, c0 + c, v[c]);
}

// ---------------------------------------------------------------------------
extern "C" void kernel_launch(void* const* d_in, const int* in_sizes, int n_in,
                              void* d_out, int out_size) {
    const float* F  = (const float*)d_in[0];
    const float* L  = (const float*)d_in[1];
    const float* W1 = (const float*)d_in[2];
    const float* b1 = (const float*)d_in[3];
    const float* W2 = (const float*)d_in[4];
    const float* b2 = (const float*)d_in[5];
    const float* Ws = (const float*)d_in[6];
    const float* bs = (const float*)d_in[7];

    convert_L<<<RT_TOTAL * 64, 256>>>(L);
    init_u0<<<NTOK / 8, 256>>>(F, W1, b1, W2, b2, Ws, bs);
    for (int s = 0; s < NSTEPS; s++) {
        dim3 grid(RT_TOTAL / 8, KSPLITS);
        step_partial<<<grid, 256>>>(s & 1);
        step_finalize<<<NTOK * 2 / 256, 256>>>(s & 1, (s + 1) & 1,
                                               s == NSTEPS - 1 ? (float*)d_out : nullptr);
    }
}

// round 10
// speedup vs baseline: 1.6009x; 1.0323x over previous
#include <cuda_runtime.h>
#include <cuda_bf16.h>
#include <cuda_fp16.h>

#define NTOK 16384
#define INF  512
#define HID  256
#define OUTF 16
#define NSTEPS 16
#define SIGMA2F 0.1f
#define LSCALE 16384.0f                 // 2^14: lifts L into e4m3 range
#define FIN_SCALE (SIGMA2F / LSCALE)
#define KSPLITS 16
#define KSEG (NTOK / KSPLITS)          // 1024
#define KT_TOTAL (NTOK / 16)           // 1024 k-tiles
#define RT_TOTAL (NTOK / 16)           // 1024 row-tiles
#define SLICES_PER_CTA (KSEG / 16)     // 64
#define INIT_CTAS (NTOK / 8)           // 2048
#define CONV_CTAS (RT_TOTAL * 64)      // 65536

// Scratch (device globals: sanctioned, no allocation)
// g_L8: L in e4m3 fragment-major: tile (rt,kt) -> 256B block, lane l -> uint2
__device__ __align__(16) uint2   g_L8[(size_t)RT_TOTAL * KT_TOTAL * 32];  // 256 MB
__device__ __align__(16) float   g_U[2][NTOK * OUTF];                     // u fp32, row-major
__device__ __align__(16) __half  g_Bfrag[2][OUTF * NTOK];                 // u f16 B-fragment-major
__device__ __align__(16) float   g_P[NTOK * OUTF];                        // partials (zero at steady state)

// ---------------------------------------------------------------------------
__device__ __forceinline__ unsigned short e4m3x2_pack(float hi, float lo) {
    unsigned short r;
    asm("cvt.rn.satfinite.e4m3x2.f32 %0, %1, %2;" : "=h"(r) : "f"(hi), "f"(lo));
    return r;
}
__device__ __forceinline__ unsigned f16x2_from_e4m3x2(unsigned short b) {
    unsigned r;
    asm("cvt.rn.f16x2.e4m3x2 %0, %1;" : "=r"(r) : "h"(b));
    return r;
}

// Helper: write one fp32 value (row r, col c) into f16 B-fragment layout
__device__ __forceinline__ void write_bfrag(__half* Bf, int r, int c, float v) {
    const int s = r >> 4, p = r & 15;
    const int g = c & 7;
    const int tt = (p & 7) >> 1;
    const int word = (p >> 3) + 2 * (c >> 3);
    const int lane = g * 4 + tt;
    Bf[s * 256 + lane * 8 + word * 2 + (p & 1)] = __float2half(v);
}

// ---------------------------------------------------------------------------
// Fused prologue kernel: blocks [0, INIT_CTAS) run init_u0 (FMA-bound);
// blocks [INIT_CTAS, INIT_CTAS+CONV_CTAS) run convert_L (DRAM-bound).
// The two populations overlap on-chip instead of running back-to-back.
// ---------------------------------------------------------------------------
#define CV_PAD 264
struct ProSmem {
    union {
        struct { float fs[8][INF]; float hs[8][HID]; } init;   // 24 KB
        float cv[16][CV_PAD];                                  // ~16.9 KB
    };
};

__global__ void __launch_bounds__(256) prologue(
    const float* __restrict__ L,
    const float* __restrict__ F,  const float* __restrict__ W1, const float* __restrict__ b1,
    const float* __restrict__ W2, const float* __restrict__ b2,
    const float* __restrict__ Ws, const float* __restrict__ bs)
{
    __shared__ ProSmem sm;
    const int tid = threadIdx.x;

    if (blockIdx.x < INIT_CTAS) {
        // ================= init_u0 =================
        float (*fs)[INF] = sm.init.fs;
        float (*hs)[HID] = sm.init.hs;
        const int rbase = blockIdx.x * 8;

        {
            const float4* Fv = (const float4*)(F + (size_t)rbase * INF);
            float4* fsv = (float4*)&fs[0][0];
            #pragma unroll 4
            for (int i = tid; i < 8 * INF / 4; i += 256) fsv[i] = Fv[i];
        }
        __syncthreads();

        {
            const int j = tid;  // 0..255
            float acc[8];
            const float bb = b1[j];
            #pragma unroll
            for (int rr = 0; rr < 8; rr++) acc[rr] = bb;
            #pragma unroll 4
            for (int k = 0; k < INF; k++) {
                const float w = W1[k * HID + j];
                #pragma unroll
                for (int rr = 0; rr < 8; rr++) acc[rr] = fmaf(fs[rr][k], w, acc[rr]);
            }
            #pragma unroll
            for (int rr = 0; rr < 8; rr++) {
                const float x = acc[rr];
                hs[rr][j] = x > 0.0f ? x : expm1f(x);
            }
        }
        __syncthreads();

        if (tid < 8 * OUTF) {
            const int rr = tid >> 4, c = tid & 15;
            float s0 = bs[c] + b2[c], s1 = 0.f, s2 = 0.f, s3 = 0.f;
            #pragma unroll 4
            for (int k = 0; k < INF; k += 4) {
                s0 = fmaf(fs[rr][k + 0], Ws[(k + 0) * OUTF + c], s0);
                s1 = fmaf(fs[rr][k + 1], Ws[(k + 1) * OUTF + c], s1);
                s2 = fmaf(fs[rr][k + 2], Ws[(k + 2) * OUTF + c], s2);
                s3 = fmaf(fs[rr][k + 3], Ws[(k + 3) * OUTF + c], s3);
            }
            #pragma unroll 4
            for (int j = 0; j < HID; j += 4) {
                s0 = fmaf(hs[rr][j + 0], W2[(j + 0) * OUTF + c], s0);
                s1 = fmaf(hs[rr][j + 1], W2[(j + 1) * OUTF + c], s1);
                s2 = fmaf(hs[rr][j + 2], W2[(j + 2) * OUTF + c], s2);
                s3 = fmaf(hs[rr][j + 3], W2[(j + 3) * OUTF + c], s3);
            }
            const float s = (s0 + s1) + (s2 + s3);
            const int r = rbase + rr;
            g_U[0][r * OUTF + c] = s;
            write_bfrag(g_Bfrag[0], r, c, s);
        }
    } else {
        // ================= convert_L =================
        float (*s)[CV_PAD] = sm.cv;
        const int blk = blockIdx.x - INIT_CTAS;   // 0..65535
        const int rt = blk >> 6;
        const int kg = blk & 63;

        const float* __restrict__ src = L + (size_t)rt * 16 * NTOK + kg * 256;
        #pragma unroll 4
        for (int j = tid; j < 16 * 64; j += 256) {
            const int row = j >> 6, c4 = j & 63;
            const float4 v = __ldcs((const float4*)(src + (size_t)row * NTOK + c4 * 4));
            *(float4*)&s[row][c4 * 4] = v;
        }
        __syncthreads();

        const int warp = tid >> 5, lane = tid & 31;
        const int g = lane >> 2, t = lane & 3;
        #pragma unroll
        for (int i = 0; i < 2; i++) {
            const int ktl = warp * 2 + i;          // local k-tile 0..15
            const int kt = kg * 16 + ktl;
            const int c = ktl * 16 + 2 * t;
            const float2 w0 = *(const float2*)&s[g][c];
            const float2 w1 = *(const float2*)&s[g + 8][c];
            const float2 w2 = *(const float2*)&s[g][c + 8];
            const float2 w3 = *(const float2*)&s[g + 8][c + 8];
            const unsigned short p0 = e4m3x2_pack(w0.y * LSCALE, w0.x * LSCALE);
            const unsigned short p1 = e4m3x2_pack(w1.y * LSCALE, w1.x * LSCALE);
            const unsigned short p2 = e4m3x2_pack(w2.y * LSCALE, w2.x * LSCALE);
            const unsigned short p3 = e4m3x2_pack(w3.y * LSCALE, w3.x * LSCALE);
            uint2 o;
            o.x = (unsigned)p0 | ((unsigned)p1 << 16);
            o.y = (unsigned)p2 | ((unsigned)p3 << 16);
            g_L8[((size_t)rt * KT_TOTAL + kt) * 32 + lane] = o;
        }
    }
}

// ---------------------------------------------------------------------------
// Kernel 3: partial GEMM (K-split), static grid (128, 16), 8 warps/CTA.
// A: fp8 frag (one LDG.64 / 16x16 tile) -> f16 in-register. B: f16 frags in smem.
// ---------------------------------------------------------------------------
__device__ __forceinline__ void mma16816h(float d[4], unsigned a0, unsigned a1,
                                          unsigned a2, unsigned a3,
                                          unsigned b0, unsigned b1) {
    asm volatile(
        "mma.sync.aligned.m16n8k16.row.col.f32.f16.f16.f32 "
        "{%0,%1,%2,%3}, {%4,%5,%6,%7}, {%8,%9}, {%0,%1,%2,%3};\n"
        : "+f"(d[0]), "+f"(d[1]), "+f"(d[2]), "+f"(d[3])
        : "r"(a0), "r"(a1), "r"(a2), "r"(a3), "r"(b0), "r"(b1));
}

__global__ void __launch_bounds__(256, 6) step_partial(int inb) {
    __shared__ uint4 sB[SLICES_PER_CTA * 32];   // 32 KB: f16 B frags for this K-range

    const int tid  = threadIdx.x;
    const int warp = tid >> 5;
    const int lane = tid & 31;

    const int rt  = blockIdx.x * 8 + warp;              // row-tile 0..1023
    const int kt0 = blockIdx.y * SLICES_PER_CTA;        // first k-tile

    {
        const uint4* __restrict__ Bg = reinterpret_cast<const uint4*>(g_Bfrag[inb]) + kt0 * 32;
        #pragma unroll 2
        for (int i = tid; i < SLICES_PER_CTA * 32; i += 256) sB[i] = Bg[i];
    }
    __syncthreads();

    const uint2* __restrict__ Af = g_L8 + ((size_t)rt * KT_TOTAL + kt0) * 32 + lane;

    float d0[4] = {0.f, 0.f, 0.f, 0.f};
    float d1[4] = {0.f, 0.f, 0.f, 0.f};

    for (int c = 0; c < SLICES_PER_CTA; c += 4) {
        uint2 w0 = __ldcs(Af + (c + 0) * 32);
        uint2 w1 = __ldcs(Af + (c + 1) * 32);
        uint2 w2 = __ldcs(Af + (c + 2) * 32);
        uint2 w3 = __ldcs(Af + (c + 3) * 32);

        #pragma unroll
        for (int q = 0; q < 4; q++) {
            const uint2 w = q == 0 ? w0 : q == 1 ? w1 : q == 2 ? w2 : w3;
            const unsigned a0 = f16x2_from_e4m3x2((unsigned short)(w.x));
            const unsigned a1 = f16x2_from_e4m3x2((unsigned short)(w.x >> 16));
            const unsigned a2 = f16x2_from_e4m3x2((unsigned short)(w.y));
            const unsigned a3 = f16x2_from_e4m3x2((unsigned short)(w.y >> 16));
            const uint4 b = sB[(c + q) * 32 + lane];
            mma16816h(d0, a0, a1, a2, a3, b.x, b.y);
            mma16816h(d1, a0, a1, a2, a3, b.z, b.w);
        }
    }

    const int g = lane >> 2, t2 = 2 * (lane & 3);
    const int r0 = rt * 16 + g, r1 = r0 + 8;
    #pragma unroll
    for (int h = 0; h < 2; h++) {
        const float* dd = h ? d1 : d0;
        const int cc = t2 + 8 * h;
        atomicAdd(&g_P[r0 * OUTF + cc],     dd[0]);
        atomicAdd(&g_P[r0 * OUTF + cc + 1], dd[1]);
        atomicAdd(&g_P[r1 * OUTF + cc],     dd[2]);
        atomicAdd(&g_P[r1 * OUTF + cc + 1], dd[3]);
    }
}

// ---------------------------------------------------------------------------
// Kernel 4: finalize. u_out = u_in - (sigma2/LSCALE) * P; rezero P; emit B-frags.
// 2 threads per row.
// ---------------------------------------------------------------------------
__global__ void __launch_bounds__(256) step_finalize(int inb, int outb, float* final_dst) {
    const int idx = blockIdx.x * 256 + threadIdx.x;   // 0..32767
    const int r = idx >> 1;
    const int c0 = (idx & 1) * 8;

    const float* __restrict__ Ui = g_U[inb] + r * OUTF + c0;
    float* __restrict__ Uo = g_U[outb] + r * OUTF + c0;
    float* __restrict__ P  = g_P + r * OUTF + c0;

    float v[8];
    #pragma unroll
    for (int i = 0; i < 2; i++) {
        float4 u4 = *(const float4*)(Ui + 4 * i);
        float4 p4 = *(const float4*)(P + 4 * i);
        v[4*i+0] = u4.x - FIN_SCALE * p4.x;
        v[4*i+1] = u4.y - FIN_SCALE * p4.y;
        v[4*i+2] = u4.z - FIN_SCALE * p4.z;
        v[4*i+3] = u4.w - FIN_SCALE * p4.w;
        *(float4*)(Uo + 4 * i) = make_float4(v[4*i+0], v[4*i+1], v[4*i+2], v[4*i+3]);
        *(float4*)(P + 4 * i) = make_float4(0.f, 0.f, 0.f, 0.f);
        if (final_dst) *(float4*)(final_dst + r * OUTF + c0 + 4 * i)
            = make_float4(v[4*i+0], v[4*i+1], v[4*i+2], v[4*i+3]);
    }
    __half* __restrict__ Bf = g_Bfrag[outb];
    #pragma unroll
    for (int c = 0; c < 8; c++) write_bfrag(Bf, r, c0 + c, v[c]);
}

// ---------------------------------------------------------------------------
extern "C" void kernel_launch(void* const* d_in, const int* in_sizes, int n_in,
                              void* d_out, int out_size) {
    const float* F  = (const float*)d_in[0];
    const float* L  = (const float*)d_in[1];
    const float* W1 = (const float*)d_in[2];
    const float* b1 = (const float*)d_in[3];
    const float* W2 = (const float*)d_in[4];
    const float* b2 = (const float*)d_in[5];
    const float* Ws = (const float*)d_in[6];
    const float* bs = (const float*)d_in[7];

    prologue<<<INIT_CTAS + CONV_CTAS, 256>>>(L, F, W1, b1, W2, b2, Ws, bs);
    for (int s = 0; s < NSTEPS; s++) {
        dim3 grid(RT_TOTAL / 8, KSPLITS);
        step_partial<<<grid, 256>>>(s & 1);
        step_finalize<<<NTOK * 2 / 256, 256>>>(s & 1, (s + 1) & 1,
                                               s == NSTEPS - 1 ? (float*)d_out : nullptr);
    }
}

// round 11
// speedup vs baseline: 1.7464x; 1.0909x over previous
#include <cuda_runtime.h>
#include <cuda_bf16.h>
#include <cuda_fp16.h>

#define NTOK 16384
#define INF  512
#define HID  256
#define OUTF 16
#define NSTEPS 16
#define SIGMA2F 0.1f
#define LSCALE 16384.0f                 // 2^14: lifts L into e4m3 range
#define FIN_SCALE (SIGMA2F / LSCALE)
#define KSPLITS 32
#define KSEG (NTOK / KSPLITS)          // 512
#define KB_TOTAL (NTOK / 32)           // 512 32-k blocks
#define RT_TOTAL (NTOK / 16)           // 1024 row-tiles
#define SLICES_PER_CTA (KSEG / 32)     // 16
#define INIT_CTAS (NTOK / 8)           // 2048
#define CONV_CTAS (RT_TOTAL * 64)      // 65536

// Scratch (device globals: sanctioned, no allocation)
// g_L8: L e4m3, k32-fragment-major: block (rt, kb) -> 512B, lane l -> uint4
//   a0 = L[g][4t..4t+3], a1 = L[g+8][4t..], a2 = L[g][16+4t..], a3 = L[g+8][16+4t..]
__device__ __align__(16) uint4          g_L8[(size_t)RT_TOTAL * KB_TOTAL * 32];  // 256 MB
__device__ __align__(16) float          g_U[2][NTOK * OUTF];                     // u fp32 master
__device__ __align__(16) unsigned char  g_B8[2][NTOK * OUTF];                    // u e4m3 B-frag-major
__device__ __align__(16) float          g_P[NTOK * OUTF];                        // partials (zero steady)

// ---------------------------------------------------------------------------
__device__ __forceinline__ unsigned short e4m3x2_pack(float hi, float lo) {
    unsigned short r;
    asm("cvt.rn.satfinite.e4m3x2.f32 %0, %1, %2;" : "=h"(r) : "f"(hi), "f"(lo));
    return r;
}
__device__ __forceinline__ unsigned pack4_e4m3(float4 f, float s) {
    const unsigned lo = e4m3x2_pack(f.y * s, f.x * s);
    const unsigned hi = e4m3x2_pack(f.w * s, f.z * s);
    return lo | (hi << 16);
}

// write one fp32 value (row r = k index, col c) into e4m3 B-fragment layout
__device__ __forceinline__ void write_bfrag8(unsigned char* Bf, int r, int c, float v) {
    const int sl = r >> 5, p = r & 31;
    const int g = c & 7;
    const int ph = p & 15;
    const int lane = g * 4 + (ph >> 2);
    const int word = (p >> 4) + 2 * (c >> 3);
    const unsigned short q = e4m3x2_pack(0.0f, v);
    Bf[sl * 512 + lane * 16 + word * 4 + (ph & 3)] = (unsigned char)(q & 0xFF);
}

// ---------------------------------------------------------------------------
// Fused prologue: blocks [0, INIT_CTAS) = init_u0; rest = convert_L (overlap).
// ---------------------------------------------------------------------------
#define CV_PAD 264
struct ProSmem {
    union {
        struct { float fs[8][INF]; float hs[8][HID]; } init;   // 24 KB
        float cv[16][CV_PAD];                                  // ~16.9 KB
    };
};

__global__ void __launch_bounds__(256) prologue(
    const float* __restrict__ L,
    const float* __restrict__ F,  const float* __restrict__ W1, const float* __restrict__ b1,
    const float* __restrict__ W2, const float* __restrict__ b2,
    const float* __restrict__ Ws, const float* __restrict__ bs)
{
    __shared__ ProSmem sm;
    const int tid = threadIdx.x;

    if (blockIdx.x < INIT_CTAS) {
        // ================= init_u0 =================
        float (*fs)[INF] = sm.init.fs;
        float (*hs)[HID] = sm.init.hs;
        const int rbase = blockIdx.x * 8;

        {
            const float4* Fv = (const float4*)(F + (size_t)rbase * INF);
            float4* fsv = (float4*)&fs[0][0];
            #pragma unroll 4
            for (int i = tid; i < 8 * INF / 4; i += 256) fsv[i] = Fv[i];
        }
        __syncthreads();

        {
            const int j = tid;
            float acc[8];
            const float bb = b1[j];
            #pragma unroll
            for (int rr = 0; rr < 8; rr++) acc[rr] = bb;
            #pragma unroll 4
            for (int k = 0; k < INF; k++) {
                const float w = W1[k * HID + j];
                #pragma unroll
                for (int rr = 0; rr < 8; rr++) acc[rr] = fmaf(fs[rr][k], w, acc[rr]);
            }
            #pragma unroll
            for (int rr = 0; rr < 8; rr++) {
                const float x = acc[rr];
                hs[rr][j] = x > 0.0f ? x : expm1f(x);
            }
        }
        __syncthreads();

        if (tid < 8 * OUTF) {
            const int rr = tid >> 4, c = tid & 15;
            float s0 = bs[c] + b2[c], s1 = 0.f, s2 = 0.f, s3 = 0.f;
            #pragma unroll 4
            for (int k = 0; k < INF; k += 4) {
                s0 = fmaf(fs[rr][k + 0], Ws[(k + 0) * OUTF + c], s0);
                s1 = fmaf(fs[rr][k + 1], Ws[(k + 1) * OUTF + c], s1);
                s2 = fmaf(fs[rr][k + 2], Ws[(k + 2) * OUTF + c], s2);
                s3 = fmaf(fs[rr][k + 3], Ws[(k + 3) * OUTF + c], s3);
            }
            #pragma unroll 4
            for (int j = 0; j < HID; j += 4) {
                s0 = fmaf(hs[rr][j + 0], W2[(j + 0) * OUTF + c], s0);
                s1 = fmaf(hs[rr][j + 1], W2[(j + 1) * OUTF + c], s1);
                s2 = fmaf(hs[rr][j + 2], W2[(j + 2) * OUTF + c], s2);
                s3 = fmaf(hs[rr][j + 3], W2[(j + 3) * OUTF + c], s3);
            }
            const float s = (s0 + s1) + (s2 + s3);
            const int r = rbase + rr;
            g_U[0][r * OUTF + c] = s;
            write_bfrag8(g_B8[0], r, c, s);
        }
    } else {
        // ================= convert_L (k32 fragment layout) =================
        float (*s)[CV_PAD] = sm.cv;
        const int blk = blockIdx.x - INIT_CTAS;   // 0..65535
        const int rt = blk >> 6;
        const int kg = blk & 63;

        const float* __restrict__ src = L + (size_t)rt * 16 * NTOK + kg * 256;
        #pragma unroll 4
        for (int j = tid; j < 16 * 64; j += 256) {
            const int row = j >> 6, c4 = j & 63;
            const float4 v = __ldcs((const float4*)(src + (size_t)row * NTOK + c4 * 4));
            *(float4*)&s[row][c4 * 4] = v;
        }
        __syncthreads();

        const int warp = tid >> 5, lane = tid & 31;
        const int g = lane >> 2, t = lane & 3;
        const int kb = kg * 8 + warp;            // global 32-k block
        const int c = warp * 32 + 4 * t;         // local col base

        const float4 f0 = *(const float4*)&s[g][c];
        const float4 f1 = *(const float4*)&s[g + 8][c];
        const float4 f2 = *(const float4*)&s[g][c + 16];
        const float4 f3 = *(const float4*)&s[g + 8][c + 16];
        uint4 o;
        o.x = pack4_e4m3(f0, LSCALE);
        o.y = pack4_e4m3(f1, LSCALE);
        o.z = pack4_e4m3(f2, LSCALE);
        o.w = pack4_e4m3(f3, LSCALE);
        g_L8[((size_t)rt * KB_TOTAL + kb) * 32 + lane] = o;
    }
}

// ---------------------------------------------------------------------------
// Kernel 3: partial GEMM, full fp8 (e4m3 x e4m3, m16n8k32). Grid (128, 32).
// ---------------------------------------------------------------------------
__device__ __forceinline__ void mma16832f8(float d[4], const uint4 a,
                                           unsigned b0, unsigned b1) {
    asm volatile(
        "mma.sync.aligned.m16n8k32.row.col.f32.e4m3.e4m3.f32 "
        "{%0,%1,%2,%3}, {%4,%5,%6,%7}, {%8,%9}, {%0,%1,%2,%3};\n"
        : "+f"(d[0]), "+f"(d[1]), "+f"(d[2]), "+f"(d[3])
        : "r"(a.x), "r"(a.y), "r"(a.z), "r"(a.w), "r"(b0), "r"(b1));
}

__global__ void __launch_bounds__(256, 6) step_partial(int inb) {
    __shared__ uint4 sB[SLICES_PER_CTA * 32];   // 8 KB: e4m3 B frags for this K-range

    const int tid  = threadIdx.x;
    const int warp = tid >> 5;
    const int lane = tid & 31;

    const int rt  = blockIdx.x * 8 + warp;              // row-tile 0..1023
    const int kb0 = blockIdx.y * SLICES_PER_CTA;        // first 32-k block

    {
        const uint4* __restrict__ Bg = reinterpret_cast<const uint4*>(g_B8[inb]) + kb0 * 32;
        #pragma unroll 2
        for (int i = tid; i < SLICES_PER_CTA * 32; i += 256) sB[i] = Bg[i];
    }
    __syncthreads();

    const uint4* __restrict__ Af = g_L8 + ((size_t)rt * KB_TOTAL + kb0) * 32 + lane;

    float d0[4] = {0.f, 0.f, 0.f, 0.f};   // cols 0..7
    float d1[4] = {0.f, 0.f, 0.f, 0.f};   // cols 8..15

    #pragma unroll 2
    for (int c = 0; c < SLICES_PER_CTA; c += 2) {
        const uint4 a0 = __ldcs(Af + (c + 0) * 32);
        const uint4 a1 = __ldcs(Af + (c + 1) * 32);
        const uint4 b0 = sB[(c + 0) * 32 + lane];
        const uint4 b1 = sB[(c + 1) * 32 + lane];
        mma16832f8(d0, a0, b0.x, b0.y);
        mma16832f8(d1, a0, b0.z, b0.w);
        mma16832f8(d0, a1, b1.x, b1.y);
        mma16832f8(d1, a1, b1.z, b1.w);
    }

    const int g = lane >> 2, t2 = 2 * (lane & 3);
    const int r0 = rt * 16 + g, r1 = r0 + 8;
    #pragma unroll
    for (int h = 0; h < 2; h++) {
        const float* dd = h ? d1 : d0;
        const int cc = t2 + 8 * h;
        atomicAdd(&g_P[r0 * OUTF + cc],     dd[0]);
        atomicAdd(&g_P[r0 * OUTF + cc + 1], dd[1]);
        atomicAdd(&g_P[r1 * OUTF + cc],     dd[2]);
        atomicAdd(&g_P[r1 * OUTF + cc + 1], dd[3]);
    }
}

// ---------------------------------------------------------------------------
// Kernel 4: finalize. u_out = u_in - (sigma2/LSCALE) * P; rezero P; emit B8.
// ---------------------------------------------------------------------------
__global__ void __launch_bounds__(256) step_finalize(int inb, int outb, float* final_dst) {
    const int idx = blockIdx.x * 256 + threadIdx.x;   // 0..32767
    const int r = idx >> 1;
    const int c0 = (idx & 1) * 8;

    const float* __restrict__ Ui = g_U[inb] + r * OUTF + c0;
    float* __restrict__ Uo = g_U[outb] + r * OUTF + c0;
    float* __restrict__ P  = g_P + r * OUTF + c0;

    float v[8];
    #pragma unroll
    for (int i = 0; i < 2; i++) {
        float4 u4 = *(const float4*)(Ui + 4 * i);
        float4 p4 = *(const float4*)(P + 4 * i);
        v[4*i+0] = u4.x - FIN_SCALE * p4.x;
        v[4*i+1] = u4.y - FIN_SCALE * p4.y;
        v[4*i+2] = u4.z - FIN_SCALE * p4.z;
        v[4*i+3] = u4.w - FIN_SCALE * p4.w;
        *(float4*)(Uo + 4 * i) = make_float4(v[4*i+0], v[4*i+1], v[4*i+2], v[4*i+3]);
        *(float4*)(P + 4 * i) = make_float4(0.f, 0.f, 0.f, 0.f);
        if (final_dst) *(float4*)(final_dst + r * OUTF + c0 + 4 * i)
            = make_float4(v[4*i+0], v[4*i+1], v[4*i+2], v[4*i+3]);
    }
    unsigned char* __restrict__ Bf = g_B8[outb];
    #pragma unroll
    for (int c = 0; c < 8; c++) write_bfrag8(Bf, r, c0 + c, v[c]);
}

// ---------------------------------------------------------------------------
extern "C" void kernel_launch(void* const* d_in, const int* in_sizes, int n_in,
                              void* d_out, int out_size) {
    const float* F  = (const float*)d_in[0];
    const float* L  = (const float*)d_in[1];
    const float* W1 = (const float*)d_in[2];
    const float* b1 = (const float*)d_in[3];
    const float* W2 = (const float*)d_in[4];
    const float* b2 = (const float*)d_in[5];
    const float* Ws = (const float*)d_in[6];
    const float* bs = (const float*)d_in[7];

    prologue<<<INIT_CTAS + CONV_CTAS, 256>>>(L, F, W1, b1, W2, b2, Ws, bs);
    for (int s = 0; s < NSTEPS; s++) {
        dim3 grid(RT_TOTAL / 8, KSPLITS);
        step_partial<<<grid, 256>>>(s & 1);
        step_finalize<<<NTOK * 2 / 256, 256>>>(s & 1, (s + 1) & 1,
                                               s == NSTEPS - 1 ? (float*)d_out : nullptr);
    }
}